// round 9
// baseline (speedup 1.0000x reference)
#include <cuda_runtime.h>
#include <cuda_fp16.h>
#include <cstdint>

// QuantizeChannelWise: x (8192,1024) f32, codebook (1024,1024) f32.
// score[m,k] = cnorm[k] - 2*dot(x_m,c_k); argmin; out = [selected ; selected].
//
// int8 IMMA GEMM (mma.sync m16n8k32, s32 accum) with fused per-tile argmin +
// candidate extraction; warp-parallel select (exact fp32 re-rank of near-ties,
// exact full-scan fallback on slot overflow); streaming gather.

#define M_Q   8192
#define K_CB  1024
#define D_DIM 1024
#define BM    128
#define BN    128
#define BKB   64               // K bytes per stage (64 int8)
#define STAGES 3
#define NITER (D_DIM / BKB)    // 16
#define NTILE (K_CB / BN)      // 8
#define CSLOT 8
#define EPS   12.0f

#define ROWSTRIDE_B 80         // bytes per smem row (conflict-free ldmatrix)
#define STAGE_BYTES (BM * ROWSTRIDE_B)            // 10240
#define SMEM_BYTES (STAGES * 2 * STAGE_BYTES)     // 61440

#define QSCALE 21.166666667f   // 127/6
#define SC2    0.0044651297f   // 2/QSCALE^2 = 2*(6/127)^2

// ---------------- device scratch ----------------
__device__ __align__(16) int8_t g_Xq[(size_t)M_Q * D_DIM];   // 8 MB
__device__ __align__(16) int8_t g_Cq[(size_t)K_CB * D_DIM];  // 1 MB
__device__ float g_cnorm[K_CB];
__device__ float g_cval[(size_t)M_Q * NTILE * CSLOT];
__device__ int   g_cidx[(size_t)M_Q * NTILE * CSLOT];
__device__ int   g_ccnt[(size_t)M_Q * NTILE];
__device__ int   g_best[M_Q];

// ---------------- helpers ----------------
__device__ __forceinline__ uint32_t smem_u32(const void* p) {
    uint32_t a;
    asm("{ .reg .u64 t; cvta.to.shared.u64 t, %1; cvt.u32.u64 %0, t; }"
        : "=r"(a) : "l"(p));
    return a;
}
__device__ __forceinline__ void cp_async16(uint32_t saddr, const void* gaddr) {
    asm volatile("cp.async.cg.shared.global [%0], [%1], 16;" :: "r"(saddr), "l"(gaddr));
}
__device__ __forceinline__ void cp_commit() { asm volatile("cp.async.commit_group;"); }
__device__ __forceinline__ void cp_wait1()  { asm volatile("cp.async.wait_group 1;"); }
__device__ __forceinline__ void ldmatrix_x4(uint32_t& r0, uint32_t& r1,
                                            uint32_t& r2, uint32_t& r3, uint32_t addr) {
    asm volatile("ldmatrix.sync.aligned.m8n8.x4.shared.b16 {%0,%1,%2,%3}, [%4];"
                 : "=r"(r0), "=r"(r1), "=r"(r2), "=r"(r3) : "r"(addr));
}
__device__ __forceinline__ void mma_s8(int& d0, int& d1, int& d2, int& d3,
                                       uint32_t a0, uint32_t a1, uint32_t a2, uint32_t a3,
                                       uint32_t b0, uint32_t b1) {
    asm volatile(
        "mma.sync.aligned.m16n8k32.row.col.s32.s8.s8.s32 "
        "{%0,%1,%2,%3}, {%4,%5,%6,%7}, {%8,%9}, {%0,%1,%2,%3};"
        : "+r"(d0), "+r"(d1), "+r"(d2), "+r"(d3)
        : "r"(a0), "r"(a1), "r"(a2), "r"(a3), "r"(b0), "r"(b1));
}
__device__ __forceinline__ uint32_t fkey(float f) {
    uint32_t u = __float_as_uint(f);
    return (u & 0x80000000u) ? ~u : (u | 0x80000000u);
}
__device__ __forceinline__ float kinv(uint32_t k) {
    uint32_t u = (k & 0x80000000u) ? (k & 0x7fffffffu) : ~k;
    return __uint_as_float(u);
}
__device__ __forceinline__ int q8(float v) {
    return __float2int_rn(fminf(fmaxf(v * QSCALE, -127.f), 127.f));
}
__device__ __forceinline__ uint32_t pack4(float x, float y, float z, float w) {
    uint32_t b0 = (uint32_t)(q8(x) & 0xff), b1 = (uint32_t)(q8(y) & 0xff);
    uint32_t b2 = (uint32_t)(q8(z) & 0xff), b3 = (uint32_t)(q8(w) & 0xff);
    return b0 | (b1 << 8) | (b2 << 16) | (b3 << 24);
}

// ---------------- convert kernels ----------------
__global__ __launch_bounds__(256) void convert_x_kernel(const float* __restrict__ X) {
    int q = blockIdx.x, t = threadIdx.x;
    float4 v = reinterpret_cast<const float4*>(X + (size_t)q * D_DIM)[t];
    reinterpret_cast<uint32_t*>(g_Xq + (size_t)q * D_DIM)[t] = pack4(v.x, v.y, v.z, v.w);
}

__global__ __launch_bounds__(256) void convert_c_kernel(const float* __restrict__ CB) {
    __shared__ float s_red[8];
    int k = blockIdx.x, t = threadIdx.x;
    float4 v = reinterpret_cast<const float4*>(CB + (size_t)k * D_DIM)[t];
    reinterpret_cast<uint32_t*>(g_Cq + (size_t)k * D_DIM)[t] = pack4(v.x, v.y, v.z, v.w);
    float ns = v.x * v.x + v.y * v.y + v.z * v.z + v.w * v.w;
    for (int off = 16; off; off >>= 1) ns += __shfl_down_sync(0xffffffffu, ns, off);
    if ((t & 31) == 0) s_red[t >> 5] = ns;
    __syncthreads();
    if (t == 0) {
        float s = 0.f;
        #pragma unroll
        for (int i = 0; i < 8; i++) s += s_red[i];
        g_cnorm[k] = s;
    }
}

// ---------------- IMMA GEMM + fused argmin/candidate epilogue ----------------
__global__ __launch_bounds__(256, 2) void gemm_kernel() {
    extern __shared__ __align__(128) char smem[];
    const int tid = threadIdx.x;
    const int wid = tid >> 5, lane = tid & 31;
    const int n0 = blockIdx.x * BN;
    const int m0 = blockIdx.y * BM;
    const int wm = wid & 3, wn = wid >> 2;
    const uint32_t sbase = smem_u32(smem);

    // loads: 512 16B-chunks per operand per stage (128 rows x 64B)
    const int r0c = tid >> 2, s0c = (tid & 3) * 16;          // bytes
    const int r1c = (tid + 256) >> 2, s1c = s0c;

    auto issue_stage = [&](int it) {
        const int buf = it % STAGES;
        const int k0 = it * BKB;
        char* As = smem + buf * 2 * STAGE_BYTES;
        char* Bs = As + STAGE_BYTES;
        cp_async16(smem_u32(As + r0c * ROWSTRIDE_B + s0c),
                   g_Xq + (size_t)(m0 + r0c) * D_DIM + k0 + s0c);
        cp_async16(smem_u32(As + r1c * ROWSTRIDE_B + s1c),
                   g_Xq + (size_t)(m0 + r1c) * D_DIM + k0 + s1c);
        cp_async16(smem_u32(Bs + r0c * ROWSTRIDE_B + s0c),
                   g_Cq + (size_t)(n0 + r0c) * D_DIM + k0 + s0c);
        cp_async16(smem_u32(Bs + r1c * ROWSTRIDE_B + s1c),
                   g_Cq + (size_t)(n0 + r1c) * D_DIM + k0 + s1c);
        cp_commit();
    };

    int d[2][8][4];
    #pragma unroll
    for (int i = 0; i < 2; i++)
        #pragma unroll
        for (int j = 0; j < 8; j++)
            #pragma unroll
            for (int r = 0; r < 4; r++) d[i][j][r] = 0;

    issue_stage(0);
    issue_stage(1);
    cp_wait1();
    __syncthreads();

    // ldmatrix addressing (byte units). Same fragment mapping as f16:
    // s8 m16n8k32 frags coincide with ldmatrix.b16 layout (4B per lane-reg).
    const int l7 = lane & 7, l3 = (lane >> 3) & 1, l4 = lane >> 4;
    const int a_row = wm * 32 + l3 * 8 + l7;
    const int a_colB = l4 * 16;                   // bytes
    const int bg = lane >> 3;
    const int b_row_base = wn * 64 + (bg >> 1) * 8 + l7;
    const int b_colB = (bg & 1) * 16;             // bytes

    for (int it = 0; it < NITER; it++) {
        if (it + 2 < NITER) issue_stage(it + 2);
        const int buf = it % STAGES;
        const uint32_t Asb = sbase + buf * 2 * STAGE_BYTES;
        const uint32_t Bsb = Asb + STAGE_BYTES;

        #pragma unroll
        for (int ks = 0; ks < 2; ks++) {          // 2 x k32 per 64B stage
            uint32_t a[2][4];
            #pragma unroll
            for (int mi = 0; mi < 2; mi++)
                ldmatrix_x4(a[mi][0], a[mi][1], a[mi][2], a[mi][3],
                    Asb + (a_row + mi * 16) * ROWSTRIDE_B + ks * 32 + a_colB);
            uint32_t b[8][2];
            #pragma unroll
            for (int j = 0; j < 4; j++) {
                uint32_t r0, r1, r2, r3;
                ldmatrix_x4(r0, r1, r2, r3,
                    Bsb + (b_row_base + 16 * j) * ROWSTRIDE_B + ks * 32 + b_colB);
                b[2 * j][0] = r0; b[2 * j][1] = r1;
                b[2 * j + 1][0] = r2; b[2 * j + 1][1] = r3;
            }
            #pragma unroll
            for (int mi = 0; mi < 2; mi++)
                #pragma unroll
                for (int nj = 0; nj < 8; nj++)
                    mma_s8(d[mi][nj][0], d[mi][nj][1], d[mi][nj][2], d[mi][nj][3],
                           a[mi][0], a[mi][1], a[mi][2], a[mi][3],
                           b[nj][0], b[nj][1]);
        }
        cp_wait1();
        __syncthreads();
    }

    // ---- fused epilogue: per-row tile-min + candidate extraction ----
    __syncthreads();
    uint32_t* s_min = reinterpret_cast<uint32_t*>(smem);
    int*      s_cnt = reinterpret_cast<int*>(s_min + BM);
    float*    s_cv  = reinterpret_cast<float*>(s_cnt + BM);
    int*      s_ci  = reinterpret_cast<int*>(s_cv + BM * CSLOT);

    for (int i = tid; i < BM; i += 256) { s_min[i] = 0xFFFFFFFFu; s_cnt[i] = 0; }
    __syncthreads();

    const int gid = lane >> 2, tig = lane & 3;
    float cn[8][2];
    #pragma unroll
    for (int nj = 0; nj < 8; nj++) {
        const int ncol = n0 + wn * 64 + nj * 8 + tig * 2;
        cn[nj][0] = __ldg(&g_cnorm[ncol]);
        cn[nj][1] = __ldg(&g_cnorm[ncol + 1]);
    }

    #pragma unroll
    for (int mi = 0; mi < 2; mi++)
        #pragma unroll
        for (int h = 0; h < 2; h++) {
            const int rl = wm * 32 + mi * 16 + gid + h * 8;
            float mn = 3.4e38f;
            #pragma unroll
            for (int nj = 0; nj < 8; nj++)
                #pragma unroll
                for (int e = 0; e < 2; e++) {
                    float sc = cn[nj][e] - SC2 * (float)d[mi][nj][h * 2 + e];
                    if (sc < mn) mn = sc;
                }
            atomicMin(&s_min[rl], fkey(mn));
        }
    __syncthreads();

    #pragma unroll
    for (int mi = 0; mi < 2; mi++)
        #pragma unroll
        for (int h = 0; h < 2; h++) {
            const int rl = wm * 32 + mi * 16 + gid + h * 8;
            const float thr = kinv(s_min[rl]) + EPS;
            #pragma unroll
            for (int nj = 0; nj < 8; nj++)
                #pragma unroll
                for (int e = 0; e < 2; e++) {
                    float sc = cn[nj][e] - SC2 * (float)d[mi][nj][h * 2 + e];
                    if (sc < thr) {
                        int p = atomicAdd(&s_cnt[rl], 1);
                        if (p < CSLOT) {
                            s_cv[rl * CSLOT + p] = sc;
                            s_ci[rl * CSLOT + p] = n0 + wn * 64 + nj * 8 + tig * 2 + e;
                        }
                    }
                }
        }
    __syncthreads();

    if (tid < BM) {
        const int c = s_cnt[tid];
        const size_t base = ((size_t)(m0 + tid) * NTILE + blockIdx.x) * CSLOT;
        g_ccnt[(size_t)(m0 + tid) * NTILE + blockIdx.x] = c;
        const int cc = (c < CSLOT) ? c : CSLOT;
        for (int s = 0; s < cc; s++) {
            g_cval[base + s] = s_cv[tid * CSLOT + s];
            g_cidx[base + s] = s_ci[tid * CSLOT + s];
        }
    }
}

// ---------------- select: one warp per query -> g_best[q] ----------------
__global__ __launch_bounds__(256) void select_kernel(
    const float* __restrict__ X, const float* __restrict__ CB
) {
    __shared__ int s_cand[8][64];
    const int warp = threadIdx.x >> 5, lane = threadIdx.x & 31;
    const int q = blockIdx.x * 8 + warp;

    const int t0 = lane >> 3, sl0 = lane & 7;
    const int t1 = (lane + 32) >> 3, sl1 = lane & 7;
    const int c0 = g_ccnt[(size_t)q * NTILE + t0];
    const int c1 = g_ccnt[(size_t)q * NTILE + t1];
    const bool over = __any_sync(0xffffffffu, (c0 > CSLOT) || (c1 > CSLOT));

    const size_t b0 = ((size_t)q * NTILE + t0) * CSLOT + sl0;
    const size_t b1 = ((size_t)q * NTILE + t1) * CSLOT + sl1;
    float v0 = (sl0 < c0) ? g_cval[b0] : 3.4e38f;
    float v1 = (sl1 < c1) ? g_cval[b1] : 3.4e38f;
    int   i0 = (sl0 < c0) ? g_cidx[b0] : 0x7fffffff;
    int   i1 = (sl1 < c1) ? g_cidx[b1] : 0x7fffffff;

    float bv = v0; int bi = i0;
    if (v1 < bv || (v1 == bv && i1 < bi)) { bv = v1; bi = i1; }
    #pragma unroll
    for (int off = 16; off; off >>= 1) {
        float ov = __shfl_down_sync(0xffffffffu, bv, off);
        int   oi = __shfl_down_sync(0xffffffffu, bi, off);
        if (ov < bv || (ov == bv && oi < bi)) { bv = ov; bi = oi; }
    }
    bv = __shfl_sync(0xffffffffu, bv, 0);
    bi = __shfl_sync(0xffffffffu, bi, 0);

    const float thr = bv + EPS;
    const uint32_t m0b = __ballot_sync(0xffffffffu, v0 < thr);
    const uint32_t m1b = __ballot_sync(0xffffffffu, v1 < thr);
    const int n0c = __popc(m0b);
    const int n = n0c + __popc(m1b);

    if (!over && n <= 1) {
        if (lane == 0) g_best[q] = bi;
        return;
    }

    float best_v = 3.4e38f; int best_i = 0x7fffffff;
    int nc = n;
    if (over) {
        nc = 0;
    } else {
        const uint32_t lt = (1u << lane) - 1u;
        if (v0 < thr) s_cand[warp][__popc(m0b & lt)] = i0;
        if (v1 < thr) s_cand[warp][n0c + __popc(m1b & lt)] = i1;
        __syncwarp();
    }

    if (nc > 0) {                   // exact fp32 re-rank
        const float4* xr = reinterpret_cast<const float4*>(X + (size_t)q * D_DIM);
        for (int ci = 0; ci < nc; ci++) {
            const int k = s_cand[warp][ci];
            const float4* cr = reinterpret_cast<const float4*>(CB + (size_t)k * D_DIM);
            float p = 0.f;
            #pragma unroll
            for (int j = 0; j < 8; j++) {
                float4 a = xr[lane + 32 * j], c = cr[lane + 32 * j];
                p += a.x * c.x + a.y * c.y + a.z * c.z + a.w * c.w;
            }
            #pragma unroll
            for (int off = 16; off; off >>= 1)
                p += __shfl_down_sync(0xffffffffu, p, off);
            if (lane == 0) {
                float sc = g_cnorm[k] - 2.0f * p;
                if (sc < best_v || (sc == best_v && k < best_i)) { best_v = sc; best_i = k; }
            }
        }
    } else {                        // overflow guard: exact full scan
        const float4* xr = reinterpret_cast<const float4*>(X + (size_t)q * D_DIM);
        for (int k = 0; k < K_CB; k++) {
            const float4* cr = reinterpret_cast<const float4*>(CB + (size_t)k * D_DIM);
            float p = 0.f;
            #pragma unroll
            for (int j = 0; j < 8; j++) {
                float4 a = xr[lane + 32 * j], c = cr[lane + 32 * j];
                p += a.x * c.x + a.y * c.y + a.z * c.z + a.w * c.w;
            }
            #pragma unroll
            for (int off = 16; off; off >>= 1)
                p += __shfl_down_sync(0xffffffffu, p, off);
            if (lane == 0) {
                float sc = g_cnorm[k] - 2.0f * p;
                if (sc < best_v || (sc == best_v && k < best_i)) { best_v = sc; best_i = k; }
            }
        }
    }
    if (lane == 0) g_best[q] = best_i;
}

// ---------------- gather ----------------
__global__ __launch_bounds__(256) void gather_kernel(
    const float* __restrict__ CB, float* __restrict__ out
) {
    const int q = blockIdx.x, t = threadIdx.x;
    const int b = g_best[q];
    const float4 w = reinterpret_cast<const float4*>(CB + (size_t)b * D_DIM)[t];
    float4* o0 = reinterpret_cast<float4*>(out) + (size_t)q * (D_DIM / 4);
    o0[t] = w;
    o0[t + (size_t)M_Q * (D_DIM / 4)] = w;
}

// ---------------- host launch ----------------
extern "C" void kernel_launch(void* const* d_in, const int* in_sizes, int n_in,
                              void* d_out, int out_size) {
    const float* x  = (const float*)d_in[0];
    const float* cb = (const float*)d_in[1];
    float* out = (float*)d_out;

    convert_x_kernel<<<M_Q, 256>>>(x);
    convert_c_kernel<<<K_CB, 256>>>(cb);

    static int smem_set = 0;
    if (!smem_set) {
        cudaFuncSetAttribute(gemm_kernel,
                             cudaFuncAttributeMaxDynamicSharedMemorySize, SMEM_BYTES);
        smem_set = 1;
    }
    gemm_kernel<<<dim3(K_CB / BN, M_Q / BM), 256, SMEM_BYTES>>>();

    select_kernel<<<M_Q / 8, 256>>>(x, cb);
    gather_kernel<<<M_Q, 256>>>(cb, out);
}

// round 16
// speedup vs baseline: 4.3327x; 4.3327x over previous
#include <cuda_runtime.h>
#include <cuda_fp16.h>
#include <cstdint>

// QuantizeChannelWise: x (8192,1024) f32, codebook (1024,1024) f32.
// score[m,k] = cnorm[k] - 2*dot(x_m,c_k); argmin; out = [selected ; selected].
//
// int8 IMMA GEMM (mma.sync m16n8k32, s32 accum) with fused per-tile argmin +
// candidate extraction; merged warp-select (exact fp32 re-rank of near-ties;
// EPS=12 validated bit-exact in R9) + block gather.
// CSLOT=16: P(tile overflow | lambda~2.4) ~ 1.5e-8; fallback is a guard only.

#define M_Q   8192
#define K_CB  1024
#define D_DIM 1024
#define BM    128
#define BN    128
#define BKB   64               // K bytes per stage (64 int8)
#define STAGES 3
#define NITER (D_DIM / BKB)    // 16
#define NTILE (K_CB / BN)      // 8
#define CSLOT 16
#define NSLOT (NTILE * CSLOT)  // 128
#define EPS   12.0f

#define ROWSTRIDE_B 80         // bytes per smem row (conflict-free ldmatrix)
#define STAGE_BYTES (BM * ROWSTRIDE_B)            // 10240
#define SMEM_BYTES (STAGES * 2 * STAGE_BYTES)     // 61440

#define QSCALE 21.166666667f   // 127/6
#define SC2    0.0044651297f   // 2/QSCALE^2

// ---------------- device scratch ----------------
__device__ __align__(16) int8_t g_Xq[(size_t)M_Q * D_DIM];   // 8 MB
__device__ __align__(16) int8_t g_Cq[(size_t)K_CB * D_DIM];  // 1 MB
__device__ float g_cnorm[K_CB];
__device__ float g_cval[(size_t)M_Q * NSLOT];                // 4 MB
__device__ int   g_cidx[(size_t)M_Q * NSLOT];                // 4 MB
__device__ int   g_ccnt[(size_t)M_Q * NTILE];

// ---------------- helpers ----------------
__device__ __forceinline__ uint32_t smem_u32(const void* p) {
    uint32_t a;
    asm("{ .reg .u64 t; cvta.to.shared.u64 t, %1; cvt.u32.u64 %0, t; }"
        : "=r"(a) : "l"(p));
    return a;
}
__device__ __forceinline__ void cp_async16(uint32_t saddr, const void* gaddr) {
    asm volatile("cp.async.cg.shared.global [%0], [%1], 16;" :: "r"(saddr), "l"(gaddr));
}
__device__ __forceinline__ void cp_commit() { asm volatile("cp.async.commit_group;"); }
__device__ __forceinline__ void cp_wait1()  { asm volatile("cp.async.wait_group 1;"); }
__device__ __forceinline__ void ldmatrix_x4(uint32_t& r0, uint32_t& r1,
                                            uint32_t& r2, uint32_t& r3, uint32_t addr) {
    asm volatile("ldmatrix.sync.aligned.m8n8.x4.shared.b16 {%0,%1,%2,%3}, [%4];"
                 : "=r"(r0), "=r"(r1), "=r"(r2), "=r"(r3) : "r"(addr));
}
__device__ __forceinline__ void mma_s8(int& d0, int& d1, int& d2, int& d3,
                                       uint32_t a0, uint32_t a1, uint32_t a2, uint32_t a3,
                                       uint32_t b0, uint32_t b1) {
    asm volatile(
        "mma.sync.aligned.m16n8k32.row.col.s32.s8.s8.s32 "
        "{%0,%1,%2,%3}, {%4,%5,%6,%7}, {%8,%9}, {%0,%1,%2,%3};"
        : "+r"(d0), "+r"(d1), "+r"(d2), "+r"(d3)
        : "r"(a0), "r"(a1), "r"(a2), "r"(a3), "r"(b0), "r"(b1));
}
__device__ __forceinline__ uint32_t fkey(float f) {
    uint32_t u = __float_as_uint(f);
    return (u & 0x80000000u) ? ~u : (u | 0x80000000u);
}
__device__ __forceinline__ float kinv(uint32_t k) {
    uint32_t u = (k & 0x80000000u) ? (k & 0x7fffffffu) : ~k;
    return __uint_as_float(u);
}
__device__ __forceinline__ int q8(float v) {
    return __float2int_rn(fminf(fmaxf(v * QSCALE, -127.f), 127.f));
}
__device__ __forceinline__ uint32_t pack4(float x, float y, float z, float w) {
    uint32_t b0 = (uint32_t)(q8(x) & 0xff), b1 = (uint32_t)(q8(y) & 0xff);
    uint32_t b2 = (uint32_t)(q8(z) & 0xff), b3 = (uint32_t)(q8(w) & 0xff);
    return b0 | (b1 << 8) | (b2 << 16) | (b3 << 24);
}

// ---------------- convert kernels ----------------
__global__ __launch_bounds__(256) void convert_x_kernel(const float* __restrict__ X) {
    int q = blockIdx.x, t = threadIdx.x;
    float4 v = reinterpret_cast<const float4*>(X + (size_t)q * D_DIM)[t];
    reinterpret_cast<uint32_t*>(g_Xq + (size_t)q * D_DIM)[t] = pack4(v.x, v.y, v.z, v.w);
}

__global__ __launch_bounds__(256) void convert_c_kernel(const float* __restrict__ CB) {
    __shared__ float s_red[8];
    int k = blockIdx.x, t = threadIdx.x;
    float4 v = reinterpret_cast<const float4*>(CB + (size_t)k * D_DIM)[t];
    reinterpret_cast<uint32_t*>(g_Cq + (size_t)k * D_DIM)[t] = pack4(v.x, v.y, v.z, v.w);
    float ns = v.x * v.x + v.y * v.y + v.z * v.z + v.w * v.w;
    for (int off = 16; off; off >>= 1) ns += __shfl_down_sync(0xffffffffu, ns, off);
    if ((t & 31) == 0) s_red[t >> 5] = ns;
    __syncthreads();
    if (t == 0) {
        float s = 0.f;
        #pragma unroll
        for (int i = 0; i < 8; i++) s += s_red[i];
        g_cnorm[k] = s;
    }
}

// ---------------- IMMA GEMM + fused argmin/candidate epilogue ----------------
__global__ __launch_bounds__(256, 2) void gemm_kernel() {
    extern __shared__ __align__(128) char smem[];
    const int tid = threadIdx.x;
    const int wid = tid >> 5, lane = tid & 31;
    const int n0 = blockIdx.x * BN;
    const int m0 = blockIdx.y * BM;
    const int wm = wid & 3, wn = wid >> 2;
    const uint32_t sbase = smem_u32(smem);

    const int r0c = tid >> 2, s0c = (tid & 3) * 16;
    const int r1c = (tid + 256) >> 2, s1c = s0c;

    auto issue_stage = [&](int it) {
        const int buf = it % STAGES;
        const int k0 = it * BKB;
        char* As = smem + buf * 2 * STAGE_BYTES;
        char* Bs = As + STAGE_BYTES;
        cp_async16(smem_u32(As + r0c * ROWSTRIDE_B + s0c),
                   g_Xq + (size_t)(m0 + r0c) * D_DIM + k0 + s0c);
        cp_async16(smem_u32(As + r1c * ROWSTRIDE_B + s1c),
                   g_Xq + (size_t)(m0 + r1c) * D_DIM + k0 + s1c);
        cp_async16(smem_u32(Bs + r0c * ROWSTRIDE_B + s0c),
                   g_Cq + (size_t)(n0 + r0c) * D_DIM + k0 + s0c);
        cp_async16(smem_u32(Bs + r1c * ROWSTRIDE_B + s1c),
                   g_Cq + (size_t)(n0 + r1c) * D_DIM + k0 + s1c);
        cp_commit();
    };

    int d[2][8][4];
    #pragma unroll
    for (int i = 0; i < 2; i++)
        #pragma unroll
        for (int j = 0; j < 8; j++)
            #pragma unroll
            for (int r = 0; r < 4; r++) d[i][j][r] = 0;

    issue_stage(0);
    issue_stage(1);
    cp_wait1();
    __syncthreads();

    const int l7 = lane & 7, l3 = (lane >> 3) & 1, l4 = lane >> 4;
    const int a_row = wm * 32 + l3 * 8 + l7;
    const int a_colB = l4 * 16;
    const int bg = lane >> 3;
    const int b_row_base = wn * 64 + (bg >> 1) * 8 + l7;
    const int b_colB = (bg & 1) * 16;

    for (int it = 0; it < NITER; it++) {
        if (it + 2 < NITER) issue_stage(it + 2);
        const int buf = it % STAGES;
        const uint32_t Asb = sbase + buf * 2 * STAGE_BYTES;
        const uint32_t Bsb = Asb + STAGE_BYTES;

        #pragma unroll
        for (int ks = 0; ks < 2; ks++) {
            uint32_t a[2][4];
            #pragma unroll
            for (int mi = 0; mi < 2; mi++)
                ldmatrix_x4(a[mi][0], a[mi][1], a[mi][2], a[mi][3],
                    Asb + (a_row + mi * 16) * ROWSTRIDE_B + ks * 32 + a_colB);
            uint32_t b[8][2];
            #pragma unroll
            for (int j = 0; j < 4; j++) {
                uint32_t r0, r1, r2, r3;
                ldmatrix_x4(r0, r1, r2, r3,
                    Bsb + (b_row_base + 16 * j) * ROWSTRIDE_B + ks * 32 + b_colB);
                b[2 * j][0] = r0; b[2 * j][1] = r1;
                b[2 * j + 1][0] = r2; b[2 * j + 1][1] = r3;
            }
            #pragma unroll
            for (int mi = 0; mi < 2; mi++)
                #pragma unroll
                for (int nj = 0; nj < 8; nj++)
                    mma_s8(d[mi][nj][0], d[mi][nj][1], d[mi][nj][2], d[mi][nj][3],
                           a[mi][0], a[mi][1], a[mi][2], a[mi][3],
                           b[nj][0], b[nj][1]);
        }
        cp_wait1();
        __syncthreads();
    }

    // ---- fused epilogue: per-row tile-min + candidate extraction ----
    __syncthreads();
    uint32_t* s_min = reinterpret_cast<uint32_t*>(smem);          // [128]
    int*      s_cnt = reinterpret_cast<int*>(s_min + BM);         // [128]
    float*    s_cv  = reinterpret_cast<float*>(s_cnt + BM);       // [128*16] 8KB
    int*      s_ci  = reinterpret_cast<int*>(s_cv + BM * CSLOT);  // [128*16] 8KB

    for (int i = tid; i < BM; i += 256) { s_min[i] = 0xFFFFFFFFu; s_cnt[i] = 0; }
    __syncthreads();

    const int gid = lane >> 2, tig = lane & 3;
    float cn[8][2];
    #pragma unroll
    for (int nj = 0; nj < 8; nj++) {
        const int ncol = n0 + wn * 64 + nj * 8 + tig * 2;
        cn[nj][0] = __ldg(&g_cnorm[ncol]);
        cn[nj][1] = __ldg(&g_cnorm[ncol + 1]);
    }

    #pragma unroll
    for (int mi = 0; mi < 2; mi++)
        #pragma unroll
        for (int h = 0; h < 2; h++) {
            const int rl = wm * 32 + mi * 16 + gid + h * 8;
            float mn = 3.4e38f;
            #pragma unroll
            for (int nj = 0; nj < 8; nj++)
                #pragma unroll
                for (int e = 0; e < 2; e++) {
                    float sc = cn[nj][e] - SC2 * (float)d[mi][nj][h * 2 + e];
                    if (sc < mn) mn = sc;
                }
            atomicMin(&s_min[rl], fkey(mn));
        }
    __syncthreads();

    #pragma unroll
    for (int mi = 0; mi < 2; mi++)
        #pragma unroll
        for (int h = 0; h < 2; h++) {
            const int rl = wm * 32 + mi * 16 + gid + h * 8;
            const float thr = kinv(s_min[rl]) + EPS;
            #pragma unroll
            for (int nj = 0; nj < 8; nj++)
                #pragma unroll
                for (int e = 0; e < 2; e++) {
                    float sc = cn[nj][e] - SC2 * (float)d[mi][nj][h * 2 + e];
                    if (sc < thr) {
                        int p = atomicAdd(&s_cnt[rl], 1);
                        if (p < CSLOT) {
                            s_cv[rl * CSLOT + p] = sc;
                            s_ci[rl * CSLOT + p] = n0 + wn * 64 + nj * 8 + tig * 2 + e;
                        }
                    }
                }
        }
    __syncthreads();

    if (tid < BM) {
        const int c = s_cnt[tid];
        const size_t base = ((size_t)(m0 + tid) * NTILE + blockIdx.x) * CSLOT;
        g_ccnt[(size_t)(m0 + tid) * NTILE + blockIdx.x] = c;
        const int cc = (c < CSLOT) ? c : CSLOT;
        for (int s = 0; s < cc; s++) {
            g_cval[base + s] = s_cv[tid * CSLOT + s];
            g_cidx[base + s] = s_ci[tid * CSLOT + s];
        }
    }
}

// ---------------- select + gather: warp selects, block writes ----------------
__global__ __launch_bounds__(256) void select_gather_kernel(
    const float* __restrict__ X, const float* __restrict__ CB, float* __restrict__ out
) {
    __shared__ int s_cand[8][NSLOT];
    __shared__ int s_best[8];
    const int warp = threadIdx.x >> 5, lane = threadIdx.x & 31;
    const int tid = threadIdx.x;
    const int q = blockIdx.x * 8 + warp;

    // 4 slots per lane: s = lane + 32*r (NSLOT=128; tile = s>>4, slot = s&15)
    float v[4]; int ix[4]; bool myover = false;
    #pragma unroll
    for (int r = 0; r < 4; r++) {
        const int s = lane + 32 * r;
        const int tile = s >> 4, sl = s & 15;
        const int c = g_ccnt[(size_t)q * NTILE + tile];
        if (c > CSLOT) myover = true;
        const bool va = sl < ((c < CSLOT) ? c : CSLOT);
        const size_t b = ((size_t)q * NTILE + tile) * CSLOT + sl;
        v[r]  = va ? g_cval[b] : 3.4e38f;
        ix[r] = va ? g_cidx[b] : 0x7fffffff;
    }
    const bool over = __any_sync(0xffffffffu, myover);

    float bv = v[0]; int bi = ix[0];
    #pragma unroll
    for (int r = 1; r < 4; r++)
        if (v[r] < bv || (v[r] == bv && ix[r] < bi)) { bv = v[r]; bi = ix[r]; }
    #pragma unroll
    for (int off = 16; off; off >>= 1) {
        float ov = __shfl_down_sync(0xffffffffu, bv, off);
        int   oi = __shfl_down_sync(0xffffffffu, bi, off);
        if (ov < bv || (ov == bv && oi < bi)) { bv = ov; bi = oi; }
    }
    bv = __shfl_sync(0xffffffffu, bv, 0);
    bi = __shfl_sync(0xffffffffu, bi, 0);

    const float thr = bv + EPS;
    uint32_t m[4]; int pre[4]; int n = 0;
    #pragma unroll
    for (int r = 0; r < 4; r++) {
        m[r] = __ballot_sync(0xffffffffu, v[r] < thr);
        pre[r] = n;
        n += __popc(m[r]);
    }

    if (!over && n <= 1) {                 // unique candidate
        if (lane == 0) s_best[warp] = bi;
    } else {
        float best_v = 3.4e38f; int best_i = 0x7fffffff;
        int nc = over ? 0 : n;
        if (!over) {
            const uint32_t lt = (1u << lane) - 1u;
            #pragma unroll
            for (int r = 0; r < 4; r++)
                if (v[r] < thr) s_cand[warp][pre[r] + __popc(m[r] & lt)] = ix[r];
            __syncwarp();
        }
        const float4* xr = reinterpret_cast<const float4*>(X + (size_t)q * D_DIM);
        if (nc > 0) {                      // exact fp32 re-rank of candidates
            for (int ci = 0; ci < nc; ci++) {
                const int k = s_cand[warp][ci];
                const float4* cr = reinterpret_cast<const float4*>(CB + (size_t)k * D_DIM);
                float p = 0.f;
                #pragma unroll
                for (int j = 0; j < 8; j++) {
                    float4 a = xr[lane + 32 * j], c = cr[lane + 32 * j];
                    p += a.x * c.x + a.y * c.y + a.z * c.z + a.w * c.w;
                }
                #pragma unroll
                for (int off = 16; off; off >>= 1)
                    p += __shfl_down_sync(0xffffffffu, p, off);
                if (lane == 0) {
                    float sc = g_cnorm[k] - 2.0f * p;
                    if (sc < best_v || (sc == best_v && k < best_i)) { best_v = sc; best_i = k; }
                }
            }
        } else {                           // overflow guard: exact scan, 4-way unrolled
            for (int k0 = 0; k0 < K_CB; k0 += 4) {
                float p0 = 0.f, p1 = 0.f, p2 = 0.f, p3 = 0.f;
                const float4* c0 = reinterpret_cast<const float4*>(CB + (size_t)(k0 + 0) * D_DIM);
                const float4* c1 = reinterpret_cast<const float4*>(CB + (size_t)(k0 + 1) * D_DIM);
                const float4* c2 = reinterpret_cast<const float4*>(CB + (size_t)(k0 + 2) * D_DIM);
                const float4* c3 = reinterpret_cast<const float4*>(CB + (size_t)(k0 + 3) * D_DIM);
                #pragma unroll
                for (int j = 0; j < 8; j++) {
                    float4 a = xr[lane + 32 * j];
                    float4 b0 = c0[lane + 32 * j], b1 = c1[lane + 32 * j];
                    float4 b2 = c2[lane + 32 * j], b3 = c3[lane + 32 * j];
                    p0 += a.x * b0.x + a.y * b0.y + a.z * b0.z + a.w * b0.w;
                    p1 += a.x * b1.x + a.y * b1.y + a.z * b1.z + a.w * b1.w;
                    p2 += a.x * b2.x + a.y * b2.y + a.z * b2.z + a.w * b2.w;
                    p3 += a.x * b3.x + a.y * b3.y + a.z * b3.z + a.w * b3.w;
                }
                #pragma unroll
                for (int off = 16; off; off >>= 1) {
                    p0 += __shfl_down_sync(0xffffffffu, p0, off);
                    p1 += __shfl_down_sync(0xffffffffu, p1, off);
                    p2 += __shfl_down_sync(0xffffffffu, p2, off);
                    p3 += __shfl_down_sync(0xffffffffu, p3, off);
                }
                if (lane == 0) {
                    float s0 = g_cnorm[k0] - 2.0f * p0;
                    float s1 = g_cnorm[k0 + 1] - 2.0f * p1;
                    float s2 = g_cnorm[k0 + 2] - 2.0f * p2;
                    float s3 = g_cnorm[k0 + 3] - 2.0f * p3;
                    if (s0 < best_v || (s0 == best_v && (k0 + 0) < best_i)) { best_v = s0; best_i = k0; }
                    if (s1 < best_v || (s1 == best_v && (k0 + 1) < best_i)) { best_v = s1; best_i = k0 + 1; }
                    if (s2 < best_v || (s2 == best_v && (k0 + 2) < best_i)) { best_v = s2; best_i = k0 + 2; }
                    if (s3 < best_v || (s3 == best_v && (k0 + 3) < best_i)) { best_v = s3; best_i = k0 + 3; }
                }
            }
        }
        if (lane == 0) s_best[warp] = best_i;
    }
    __syncthreads();

    // block-cooperative gather: 8 queries x 1024 floats x 2 halves
    #pragma unroll
    for (int w = 0; w < 8; w++) {
        const int b = s_best[w];
        const int qq = blockIdx.x * 8 + w;
        const float4 val = reinterpret_cast<const float4*>(CB + (size_t)b * D_DIM)[tid];
        float4* o0 = reinterpret_cast<float4*>(out) + (size_t)qq * (D_DIM / 4);
        o0[tid] = val;
        o0[tid + (size_t)M_Q * (D_DIM / 4)] = val;
    }
}

// ---------------- host launch ----------------
extern "C" void kernel_launch(void* const* d_in, const int* in_sizes, int n_in,
                              void* d_out, int out_size) {
    const float* x  = (const float*)d_in[0];
    const float* cb = (const float*)d_in[1];
    float* out = (float*)d_out;

    convert_x_kernel<<<M_Q, 256>>>(x);
    convert_c_kernel<<<K_CB, 256>>>(cb);

    static int smem_set = 0;
    if (!smem_set) {
        cudaFuncSetAttribute(gemm_kernel,
                             cudaFuncAttributeMaxDynamicSharedMemorySize, SMEM_BYTES);
        smem_set = 1;
    }
    gemm_kernel<<<dim3(K_CB / BN, M_Q / BM), 256, SMEM_BYTES>>>();

    select_gather_kernel<<<M_Q / 8, 256>>>(x, cb, out);
}

// round 17
// speedup vs baseline: 7.7102x; 1.7795x over previous
#include <cuda_runtime.h>
#include <cuda_fp16.h>
#include <cstdint>

// QuantizeChannelWise: x (8192,1024) f32, codebook (1024,1024) f32.
// score[m,k] = cnorm[k] - 2*dot(x_m,c_k); argmin; out = [selected ; selected].
//
// PROVEN CONFIG (R6) + merged select/gather:
// fp16 HMMA GEMM (fp32 accum) with fused per-tile argmin + candidate
// extraction (EPS=1.5 ~ 40 sigma of fp16 score error; CSLOT=8);
// merged warp-select (exact fp32 re-rank of near-ties) + block gather.

#define M_Q   8192
#define K_CB  1024
#define D_DIM 1024
#define BM    128
#define BN    128
#define BK    32
#define STAGES 3
#define NITER (D_DIM / BK)     // 32
#define NTILE (K_CB / BN)      // 8
#define CSLOT 8
#define NSLOT (NTILE * CSLOT)  // 64
#define EPS   1.5f

#define A_ROWSTRIDE 40         // fp16 units (80B) -> conflict-free ldmatrix
#define STAGE_H (BM * A_ROWSTRIDE)
#define SMEM_BYTES (STAGES * 2 * STAGE_H * 2)   // 61440

// ---------------- device scratch ----------------
__device__ __align__(16) __half g_Xh[(size_t)M_Q * D_DIM];    // 16 MB
__device__ __align__(16) __half g_Ch[(size_t)K_CB * D_DIM];   // 2 MB
__device__ float g_cnorm[K_CB];
__device__ float g_cval[(size_t)M_Q * NSLOT];                 // 2 MB
__device__ int   g_cidx[(size_t)M_Q * NSLOT];                 // 2 MB
__device__ int   g_ccnt[(size_t)M_Q * NTILE];

// ---------------- helpers ----------------
__device__ __forceinline__ uint32_t smem_u32(const void* p) {
    uint32_t a;
    asm("{ .reg .u64 t; cvta.to.shared.u64 t, %1; cvt.u32.u64 %0, t; }"
        : "=r"(a) : "l"(p));
    return a;
}
__device__ __forceinline__ void cp_async16(uint32_t saddr, const void* gaddr) {
    asm volatile("cp.async.cg.shared.global [%0], [%1], 16;" :: "r"(saddr), "l"(gaddr));
}
__device__ __forceinline__ void cp_commit() { asm volatile("cp.async.commit_group;"); }
__device__ __forceinline__ void cp_wait1()  { asm volatile("cp.async.wait_group 1;"); }
__device__ __forceinline__ void ldmatrix_x4(uint32_t& r0, uint32_t& r1,
                                            uint32_t& r2, uint32_t& r3, uint32_t addr) {
    asm volatile("ldmatrix.sync.aligned.m8n8.x4.shared.b16 {%0,%1,%2,%3}, [%4];"
                 : "=r"(r0), "=r"(r1), "=r"(r2), "=r"(r3) : "r"(addr));
}
__device__ __forceinline__ void mma_f16(float& d0, float& d1, float& d2, float& d3,
                                        uint32_t a0, uint32_t a1, uint32_t a2, uint32_t a3,
                                        uint32_t b0, uint32_t b1) {
    asm volatile(
        "mma.sync.aligned.m16n8k16.row.col.f32.f16.f16.f32 "
        "{%0,%1,%2,%3}, {%4,%5,%6,%7}, {%8,%9}, {%0,%1,%2,%3};"
        : "+f"(d0), "+f"(d1), "+f"(d2), "+f"(d3)
        : "r"(a0), "r"(a1), "r"(a2), "r"(a3), "r"(b0), "r"(b1));
}
__device__ __forceinline__ uint32_t fkey(float f) {
    uint32_t u = __float_as_uint(f);
    return (u & 0x80000000u) ? ~u : (u | 0x80000000u);
}
__device__ __forceinline__ float kinv(uint32_t k) {
    uint32_t u = (k & 0x80000000u) ? (k & 0x7fffffffu) : ~k;
    return __uint_as_float(u);
}

// ---------------- convert kernels ----------------
__global__ __launch_bounds__(256) void convert_x_kernel(const float* __restrict__ X) {
    int q = blockIdx.x, t = threadIdx.x;
    float4 v = reinterpret_cast<const float4*>(X + (size_t)q * D_DIM)[t];
    union { __half h[4]; uint2 u; } H;
    H.h[0] = __float2half(v.x); H.h[1] = __float2half(v.y);
    H.h[2] = __float2half(v.z); H.h[3] = __float2half(v.w);
    reinterpret_cast<uint2*>(g_Xh + (size_t)q * D_DIM)[t] = H.u;
}

__global__ __launch_bounds__(256) void convert_c_kernel(const float* __restrict__ CB) {
    __shared__ float s_red[8];
    int k = blockIdx.x, t = threadIdx.x;
    float4 v = reinterpret_cast<const float4*>(CB + (size_t)k * D_DIM)[t];
    union { __half h[4]; uint2 u; } H;
    H.h[0] = __float2half(v.x); H.h[1] = __float2half(v.y);
    H.h[2] = __float2half(v.z); H.h[3] = __float2half(v.w);
    reinterpret_cast<uint2*>(g_Ch + (size_t)k * D_DIM)[t] = H.u;
    float ns = v.x * v.x + v.y * v.y + v.z * v.z + v.w * v.w;
    for (int off = 16; off; off >>= 1) ns += __shfl_down_sync(0xffffffffu, ns, off);
    if ((t & 31) == 0) s_red[t >> 5] = ns;
    __syncthreads();
    if (t == 0) {
        float s = 0.f;
        #pragma unroll
        for (int i = 0; i < 8; i++) s += s_red[i];
        g_cnorm[k] = s;
    }
}

// ---------------- fp16 HMMA GEMM + fused argmin/candidate epilogue ----------------
__global__ __launch_bounds__(256, 2) void gemm_kernel() {
    extern __shared__ __align__(128) __half smem[];
    const int tid = threadIdx.x;
    const int wid = tid >> 5, lane = tid & 31;
    const int n0 = blockIdx.x * BN;
    const int m0 = blockIdx.y * BM;
    const int wm = wid & 3, wn = wid >> 2;
    const uint32_t sbase = smem_u32(smem);

    const int r0c = tid >> 2, s0c = (tid & 3) * 8;
    const int r1c = (tid + 256) >> 2, s1c = s0c;

    auto issue_stage = [&](int it) {
        const int buf = it % STAGES;
        const int k0 = it * BK;
        __half* As = smem + buf * 2 * STAGE_H;
        __half* Bs = As + STAGE_H;
        cp_async16(smem_u32(As + r0c * A_ROWSTRIDE + s0c),
                   g_Xh + (size_t)(m0 + r0c) * D_DIM + k0 + s0c);
        cp_async16(smem_u32(As + r1c * A_ROWSTRIDE + s1c),
                   g_Xh + (size_t)(m0 + r1c) * D_DIM + k0 + s1c);
        cp_async16(smem_u32(Bs + r0c * A_ROWSTRIDE + s0c),
                   g_Ch + (size_t)(n0 + r0c) * D_DIM + k0 + s0c);
        cp_async16(smem_u32(Bs + r1c * A_ROWSTRIDE + s1c),
                   g_Ch + (size_t)(n0 + r1c) * D_DIM + k0 + s1c);
        cp_commit();
    };

    float d[2][8][4];
    #pragma unroll
    for (int i = 0; i < 2; i++)
        #pragma unroll
        for (int j = 0; j < 8; j++)
            #pragma unroll
            for (int r = 0; r < 4; r++) d[i][j][r] = 0.f;

    issue_stage(0);
    issue_stage(1);
    cp_wait1();
    __syncthreads();

    const int l7 = lane & 7, l3 = (lane >> 3) & 1, l4 = lane >> 4;
    const int a_row = wm * 32 + l3 * 8 + l7;
    const int a_col = l4 * 8;
    const int bg = lane >> 3;
    const int b_row_base = wn * 64 + (bg >> 1) * 8 + l7;
    const int b_col = (bg & 1) * 8;

    for (int it = 0; it < NITER; it++) {
        if (it + 2 < NITER) issue_stage(it + 2);
        const int buf = it % STAGES;
        const uint32_t Asb = sbase + (buf * 2 * STAGE_H) * 2;
        const uint32_t Bsb = Asb + STAGE_H * 2;

        #pragma unroll
        for (int ks = 0; ks < 2; ks++) {
            uint32_t a[2][4];
            #pragma unroll
            for (int mi = 0; mi < 2; mi++)
                ldmatrix_x4(a[mi][0], a[mi][1], a[mi][2], a[mi][3],
                    Asb + ((a_row + mi * 16) * A_ROWSTRIDE + ks * 16 + a_col) * 2);
            uint32_t b[8][2];
            #pragma unroll
            for (int j = 0; j < 4; j++) {
                uint32_t r0, r1, r2, r3;
                ldmatrix_x4(r0, r1, r2, r3,
                    Bsb + ((b_row_base + 16 * j) * A_ROWSTRIDE + ks * 16 + b_col) * 2);
                b[2 * j][0] = r0; b[2 * j][1] = r1;
                b[2 * j + 1][0] = r2; b[2 * j + 1][1] = r3;
            }
            #pragma unroll
            for (int mi = 0; mi < 2; mi++)
                #pragma unroll
                for (int nj = 0; nj < 8; nj++)
                    mma_f16(d[mi][nj][0], d[mi][nj][1], d[mi][nj][2], d[mi][nj][3],
                            a[mi][0], a[mi][1], a[mi][2], a[mi][3],
                            b[nj][0], b[nj][1]);
        }
        cp_wait1();
        __syncthreads();
    }

    // ---- fused epilogue: per-row tile-min + candidate extraction ----
    __syncthreads();
    uint32_t* s_min = reinterpret_cast<uint32_t*>(smem);          // [128]
    int*      s_cnt = reinterpret_cast<int*>(s_min + BM);         // [128]
    float*    s_cv  = reinterpret_cast<float*>(s_cnt + BM);       // [128*8]
    int*      s_ci  = reinterpret_cast<int*>(s_cv + BM * CSLOT);  // [128*8]

    for (int i = tid; i < BM; i += 256) { s_min[i] = 0xFFFFFFFFu; s_cnt[i] = 0; }
    __syncthreads();

    const int gid = lane >> 2, tig = lane & 3;
    float cn[8][2];
    #pragma unroll
    for (int nj = 0; nj < 8; nj++) {
        const int ncol = n0 + wn * 64 + nj * 8 + tig * 2;
        cn[nj][0] = __ldg(&g_cnorm[ncol]);
        cn[nj][1] = __ldg(&g_cnorm[ncol + 1]);
    }

    #pragma unroll
    for (int mi = 0; mi < 2; mi++)
        #pragma unroll
        for (int h = 0; h < 2; h++) {
            const int rl = wm * 32 + mi * 16 + gid + h * 8;
            float mn = 3.4e38f;
            #pragma unroll
            for (int nj = 0; nj < 8; nj++)
                #pragma unroll
                for (int e = 0; e < 2; e++) {
                    float sc = cn[nj][e] - 2.0f * d[mi][nj][h * 2 + e];
                    if (sc < mn) mn = sc;
                }
            atomicMin(&s_min[rl], fkey(mn));
        }
    __syncthreads();

    #pragma unroll
    for (int mi = 0; mi < 2; mi++)
        #pragma unroll
        for (int h = 0; h < 2; h++) {
            const int rl = wm * 32 + mi * 16 + gid + h * 8;
            const float thr = kinv(s_min[rl]) + EPS;
            #pragma unroll
            for (int nj = 0; nj < 8; nj++)
                #pragma unroll
                for (int e = 0; e < 2; e++) {
                    float sc = cn[nj][e] - 2.0f * d[mi][nj][h * 2 + e];
                    if (sc < thr) {
                        int p = atomicAdd(&s_cnt[rl], 1);
                        if (p < CSLOT) {
                            s_cv[rl * CSLOT + p] = sc;
                            s_ci[rl * CSLOT + p] = n0 + wn * 64 + nj * 8 + tig * 2 + e;
                        }
                    }
                }
        }
    __syncthreads();

    if (tid < BM) {
        const int c = s_cnt[tid];
        const size_t base = ((size_t)(m0 + tid) * NTILE + blockIdx.x) * CSLOT;
        g_ccnt[(size_t)(m0 + tid) * NTILE + blockIdx.x] = c;
        const int cc = (c < CSLOT) ? c : CSLOT;
        for (int s = 0; s < cc; s++) {
            g_cval[base + s] = s_cv[tid * CSLOT + s];
            g_cidx[base + s] = s_ci[tid * CSLOT + s];
        }
    }
}

// ---------------- select + gather: warp selects, block writes ----------------
__global__ __launch_bounds__(256) void select_gather_kernel(
    const float* __restrict__ X, const float* __restrict__ CB, float* __restrict__ out
) {
    __shared__ int s_cand[8][NSLOT];
    __shared__ int s_best[8];
    const int warp = threadIdx.x >> 5, lane = threadIdx.x & 31;
    const int tid = threadIdx.x;
    const int q = blockIdx.x * 8 + warp;

    // 2 slots per lane: s = lane + 32*r (NSLOT=64; tile = s>>3, slot = s&7)
    float v[2]; int ix[2]; bool myover = false;
    #pragma unroll
    for (int r = 0; r < 2; r++) {
        const int s = lane + 32 * r;
        const int tile = s >> 3, sl = s & 7;
        const int c = g_ccnt[(size_t)q * NTILE + tile];
        if (c > CSLOT) myover = true;
        const bool va = sl < ((c < CSLOT) ? c : CSLOT);
        const size_t b = ((size_t)q * NTILE + tile) * CSLOT + sl;
        v[r]  = va ? g_cval[b] : 3.4e38f;
        ix[r] = va ? g_cidx[b] : 0x7fffffff;
    }
    const bool over = __any_sync(0xffffffffu, myover);

    float bv = v[0]; int bi = ix[0];
    if (v[1] < bv || (v[1] == bv && ix[1] < bi)) { bv = v[1]; bi = ix[1]; }
    #pragma unroll
    for (int off = 16; off; off >>= 1) {
        float ov = __shfl_down_sync(0xffffffffu, bv, off);
        int   oi = __shfl_down_sync(0xffffffffu, bi, off);
        if (ov < bv || (ov == bv && oi < bi)) { bv = ov; bi = oi; }
    }
    bv = __shfl_sync(0xffffffffu, bv, 0);
    bi = __shfl_sync(0xffffffffu, bi, 0);

    const float thr = bv + EPS;
    uint32_t m[2]; int pre[2]; int n = 0;
    #pragma unroll
    for (int r = 0; r < 2; r++) {
        m[r] = __ballot_sync(0xffffffffu, v[r] < thr);
        pre[r] = n;
        n += __popc(m[r]);
    }

    if (!over && n <= 1) {                 // fast path: unique candidate
        if (lane == 0) s_best[warp] = bi;
    } else {
        float best_v = 3.4e38f; int best_i = 0x7fffffff;
        int nc = over ? 0 : n;
        if (!over) {
            const uint32_t lt = (1u << lane) - 1u;
            #pragma unroll
            for (int r = 0; r < 2; r++)
                if (v[r] < thr) s_cand[warp][pre[r] + __popc(m[r] & lt)] = ix[r];
            __syncwarp();
        }
        const float4* xr = reinterpret_cast<const float4*>(X + (size_t)q * D_DIM);
        if (nc > 0) {                      // exact fp32 re-rank of candidates
            for (int ci = 0; ci < nc; ci++) {
                const int k = s_cand[warp][ci];
                const float4* cr = reinterpret_cast<const float4*>(CB + (size_t)k * D_DIM);
                float p = 0.f;
                #pragma unroll
                for (int j = 0; j < 8; j++) {
                    float4 a = xr[lane + 32 * j], c = cr[lane + 32 * j];
                    p += a.x * c.x + a.y * c.y + a.z * c.z + a.w * c.w;
                }
                #pragma unroll
                for (int off = 16; off; off >>= 1)
                    p += __shfl_down_sync(0xffffffffu, p, off);
                if (lane == 0) {
                    float sc = g_cnorm[k] - 2.0f * p;
                    if (sc < best_v || (sc == best_v && k < best_i)) { best_v = sc; best_i = k; }
                }
            }
        } else {                           // overflow guard: exact scan, 4-way unrolled
            for (int k0 = 0; k0 < K_CB; k0 += 4) {
                float p0 = 0.f, p1 = 0.f, p2 = 0.f, p3 = 0.f;
                const float4* c0 = reinterpret_cast<const float4*>(CB + (size_t)(k0 + 0) * D_DIM);
                const float4* c1 = reinterpret_cast<const float4*>(CB + (size_t)(k0 + 1) * D_DIM);
                const float4* c2 = reinterpret_cast<const float4*>(CB + (size_t)(k0 + 2) * D_DIM);
                const float4* c3 = reinterpret_cast<const float4*>(CB + (size_t)(k0 + 3) * D_DIM);
                #pragma unroll
                for (int j = 0; j < 8; j++) {
                    float4 a = xr[lane + 32 * j];
                    float4 b0 = c0[lane + 32 * j], b1 = c1[lane + 32 * j];
                    float4 b2 = c2[lane + 32 * j], b3 = c3[lane + 32 * j];
                    p0 += a.x * b0.x + a.y * b0.y + a.z * b0.z + a.w * b0.w;
                    p1 += a.x * b1.x + a.y * b1.y + a.z * b1.z + a.w * b1.w;
                    p2 += a.x * b2.x + a.y * b2.y + a.z * b2.z + a.w * b2.w;
                    p3 += a.x * b3.x + a.y * b3.y + a.z * b3.z + a.w * b3.w;
                }
                #pragma unroll
                for (int off = 16; off; off >>= 1) {
                    p0 += __shfl_down_sync(0xffffffffu, p0, off);
                    p1 += __shfl_down_sync(0xffffffffu, p1, off);
                    p2 += __shfl_down_sync(0xffffffffu, p2, off);
                    p3 += __shfl_down_sync(0xffffffffu, p3, off);
                }
                if (lane == 0) {
                    float s0 = g_cnorm[k0] - 2.0f * p0;
                    float s1 = g_cnorm[k0 + 1] - 2.0f * p1;
                    float s2 = g_cnorm[k0 + 2] - 2.0f * p2;
                    float s3 = g_cnorm[k0 + 3] - 2.0f * p3;
                    if (s0 < best_v || (s0 == best_v && (k0 + 0) < best_i)) { best_v = s0; best_i = k0; }
                    if (s1 < best_v || (s1 == best_v && (k0 + 1) < best_i)) { best_v = s1; best_i = k0 + 1; }
                    if (s2 < best_v || (s2 == best_v && (k0 + 2) < best_i)) { best_v = s2; best_i = k0 + 2; }
                    if (s3 < best_v || (s3 == best_v && (k0 + 3) < best_i)) { best_v = s3; best_i = k0 + 3; }
                }
            }
        }
        if (lane == 0) s_best[warp] = best_i;
    }
    __syncthreads();

    // block-cooperative gather: 8 queries x 1024 floats x 2 halves
    #pragma unroll
    for (int w = 0; w < 8; w++) {
        const int b = s_best[w];
        const int qq = blockIdx.x * 8 + w;
        const float4 val = reinterpret_cast<const float4*>(CB + (size_t)b * D_DIM)[tid];
        float4* o0 = reinterpret_cast<float4*>(out) + (size_t)qq * (D_DIM / 4);
        o0[tid] = val;
        o0[tid + (size_t)M_Q * (D_DIM / 4)] = val;
    }
}

// ---------------- host launch ----------------
extern "C" void kernel_launch(void* const* d_in, const int* in_sizes, int n_in,
                              void* d_out, int out_size) {
    const float* x  = (const float*)d_in[0];
    const float* cb = (const float*)d_in[1];
    float* out = (float*)d_out;

    convert_x_kernel<<<M_Q, 256>>>(x);
    convert_c_kernel<<<K_CB, 256>>>(cb);

    static int smem_set = 0;
    if (!smem_set) {
        cudaFuncSetAttribute(gemm_kernel,
                             cudaFuncAttributeMaxDynamicSharedMemorySize, SMEM_BYTES);
        smem_set = 1;
    }
    gemm_kernel<<<dim3(K_CB / BN, M_Q / BM), 256, SMEM_BYTES>>>();

    select_gather_kernel<<<M_Q / 8, 256>>>(x, cb, out);
}